// round 1
// baseline (speedup 1.0000x reference)
#include <cuda_runtime.h>

#define BB 32768
#define TT 78
#define HH 27
#define GG 108   // 4*H

// Ping-pong scratch for inter-layer activations (allowed: __device__ globals)
static __device__ float g_buf0[(size_t)BB * TT * HH];
static __device__ float g_buf1[(size_t)BB * TT * HH];

__device__ __forceinline__ float sigf(float x) {
    return __fdividef(1.0f, 1.0f + __expf(-x));
}
__device__ __forceinline__ float tanhfast(float x) {
    // tanh(x) = 2*sigmoid(2x) - 1 ; error ~1e-6 rel, fine vs 1e-3 threshold
    return __fdividef(2.0f, 1.0f + __expf(-2.0f * x)) - 1.0f;
}

// One LSTM layer over the full sequence; optional fused final linear head.
// in_sel: 0 = external x, 1 = g_buf0, 2 = g_buf1
// out_sel: 0 = d_out (apply linear head), 1 = g_buf0, 2 = g_buf1
__global__ void __launch_bounds__(128)
lstm_layer_kernel(const float* __restrict__ xin,
                  const float* __restrict__ h0,
                  const float* __restrict__ c0,
                  const float* __restrict__ Wih,
                  const float* __restrict__ Whh,
                  const float* __restrict__ bih,
                  const float* __restrict__ bhh,
                  const float* __restrict__ Wl,
                  const float* __restrict__ bl,
                  int in_sel, int out_sel, float* dout)
{
    // Gate-packed weights: Wp[k][j] = (W_i[j,k], W_f[j,k], W_g[j,k], W_o[j,k])
    // k in [0,27) -> Wih, k in [27,54) -> Whh. One broadcast LDS.128 feeds 4 FMAs.
    __shared__ float4 Wp[2 * HH][HH];
    __shared__ float4 b4[HH];
    __shared__ float  Wls[HH][HH];
    __shared__ float  bls[HH];

    const int tid = threadIdx.x;

    for (int i = tid; i < 2 * HH * HH; i += 128) {
        int k = i / HH, j = i % HH;
        float4 w;
        if (k < HH) {
            w.x = Wih[(0 * HH + j) * HH + k];
            w.y = Wih[(1 * HH + j) * HH + k];
            w.z = Wih[(2 * HH + j) * HH + k];
            w.w = Wih[(3 * HH + j) * HH + k];
        } else {
            int kk = k - HH;
            w.x = Whh[(0 * HH + j) * HH + kk];
            w.y = Whh[(1 * HH + j) * HH + kk];
            w.z = Whh[(2 * HH + j) * HH + kk];
            w.w = Whh[(3 * HH + j) * HH + kk];
        }
        Wp[k][j] = w;
    }
    if (tid < HH) {
        b4[tid] = make_float4(bih[0 * HH + tid] + bhh[0 * HH + tid],
                              bih[1 * HH + tid] + bhh[1 * HH + tid],
                              bih[2 * HH + tid] + bhh[2 * HH + tid],
                              bih[3 * HH + tid] + bhh[3 * HH + tid]);
        bls[tid] = bl[tid];
    }
    if (out_sel == 0) {
        for (int i = tid; i < HH * HH; i += 128) Wls[i / HH][i % HH] = Wl[i];
    }
    __syncthreads();

    const float* in  = (in_sel  == 0) ? xin  : (in_sel  == 1 ? g_buf0 : g_buf1);
    float*       out = (out_sel == 0) ? dout : (out_sel == 1 ? g_buf0 : g_buf1);

    const int b = blockIdx.x * 128 + tid;   // grid is exactly B/128

    float h[HH], c[HH];
#pragma unroll
    for (int j = 0; j < HH; ++j) {
        h[j] = h0[(size_t)b * HH + j];
        c[j] = c0[(size_t)b * HH + j];
    }

    const float* xp = in  + (size_t)b * TT * HH;
    float*       op = out + (size_t)b * TT * HH;

    // Prefetch x for t=0
    float xv[HH];
#pragma unroll
    for (int k = 0; k < HH; ++k) xv[k] = xp[k];

    for (int t = 0; t < TT; ++t) {
        // Prefetch next timestep's x while this step computes (hides DRAM latency)
        float xn[HH];
        if (t + 1 < TT) {
#pragma unroll
            for (int k = 0; k < HH; ++k) xn[k] = xp[(t + 1) * HH + k];
        }

        float hn[HH];
#pragma unroll
        for (int j = 0; j < HH; ++j) {
            float4 acc = b4[j];
#pragma unroll
            for (int k = 0; k < HH; ++k) {
                float4 w = Wp[k][j];
                acc.x = fmaf(w.x, xv[k], acc.x);
                acc.y = fmaf(w.y, xv[k], acc.y);
                acc.z = fmaf(w.z, xv[k], acc.z);
                acc.w = fmaf(w.w, xv[k], acc.w);
            }
#pragma unroll
            for (int k = 0; k < HH; ++k) {
                float4 w = Wp[HH + k][j];
                acc.x = fmaf(w.x, h[k], acc.x);
                acc.y = fmaf(w.y, h[k], acc.y);
                acc.z = fmaf(w.z, h[k], acc.z);
                acc.w = fmaf(w.w, h[k], acc.w);
            }
            float ig = sigf(acc.x);
            float fg = sigf(acc.y);
            float gg = tanhfast(acc.z);
            float og = sigf(acc.w);
            float cn = fmaf(fg, c[j], ig * gg);
            c[j]  = cn;
            hn[j] = og * tanhfast(cn);
        }

        if (out_sel == 0) {
            // Fused final linear: out[o] = sum_j hn[j] * Wl[o][j] + bl[o]
#pragma unroll
            for (int o = 0; o < HH; ++o) {
                float acc = bls[o];
#pragma unroll
                for (int j = 0; j < HH; ++j) acc = fmaf(Wls[o][j], hn[j], acc);
                op[t * HH + o] = acc;
            }
        } else {
#pragma unroll
            for (int j = 0; j < HH; ++j) op[t * HH + j] = hn[j];
        }

#pragma unroll
        for (int j = 0; j < HH; ++j) h[j] = hn[j];
        if (t + 1 < TT) {
#pragma unroll
            for (int k = 0; k < HH; ++k) xv[k] = xn[k];
        }
    }
}

extern "C" void kernel_launch(void* const* d_in, const int* in_sizes, int n_in,
                              void* d_out, int out_size)
{
    const float* x   = (const float*)d_in[0];
    const float* h0  = (const float*)d_in[1];   // [3, B, H]
    const float* c0  = (const float*)d_in[2];   // [3, B, H]
    const float* Wih = (const float*)d_in[3];   // [3, 4H, H]
    const float* Whh = (const float*)d_in[4];   // [3, 4H, H]
    const float* bih = (const float*)d_in[5];   // [3, 4H]
    const float* bhh = (const float*)d_in[6];   // [3, 4H]
    const float* Wl  = (const float*)d_in[7];   // [H, H]
    const float* bl  = (const float*)d_in[8];   // [H]
    float* out = (float*)d_out;

    const size_t stateStride = (size_t)BB * HH;
    const size_t wStride = (size_t)GG * HH;
    const size_t bStride = (size_t)GG;

    dim3 grid(BB / 128), blk(128);

    // Layer 0: x -> buf0
    lstm_layer_kernel<<<grid, blk>>>(x, h0, c0, Wih, Whh, bih, bhh,
                                     Wl, bl, /*in*/0, /*out*/1, out);
    // Layer 1: buf0 -> buf1
    lstm_layer_kernel<<<grid, blk>>>(x, h0 + stateStride, c0 + stateStride,
                                     Wih + wStride, Whh + wStride,
                                     bih + bStride, bhh + bStride,
                                     Wl, bl, /*in*/1, /*out*/2, out);
    // Layer 2: buf1 -> d_out, fused linear head
    lstm_layer_kernel<<<grid, blk>>>(x, h0 + 2 * stateStride, c0 + 2 * stateStride,
                                     Wih + 2 * wStride, Whh + 2 * wStride,
                                     bih + 2 * bStride, bhh + 2 * bStride,
                                     Wl, bl, /*in*/2, /*out*/0, out);
}

// round 3
// speedup vs baseline: 1.4226x; 1.4226x over previous
#include <cuda_runtime.h>

#define BB 32768
#define TT 78
#define HH 27
#define GG 108   // 4*H

// Scratch (device globals; accessed ONLY from device code)
static __device__ float4 g_xg[(size_t)BB * TT * HH];   // gate preactivations, gate-packed
static __device__ float  g_hbuf[(size_t)BB * TT * HH]; // inter-layer activations

__device__ __forceinline__ float sigf(float x) {
    return __fdividef(1.0f, 1.0f + __expf(-x));
}
__device__ __forceinline__ float tanhfast(float x) {
    return __fdividef(2.0f, 1.0f + __expf(-2.0f * x)) - 1.0f;
}

// ---------- packed f32x2 helpers ----------
__device__ __forceinline__ unsigned long long pack2(float lo, float hi) {
    unsigned long long r;
    asm("mov.b64 %0, {%1, %2};" : "=l"(r) : "f"(lo), "f"(hi));
    return r;
}
__device__ __forceinline__ void unpack2(unsigned long long v, float& lo, float& hi) {
    asm("mov.b64 {%0, %1}, %2;" : "=f"(lo), "=f"(hi) : "l"(v));
}
__device__ __forceinline__ unsigned long long fma2(unsigned long long a, unsigned long long b,
                                                   unsigned long long c) {
    unsigned long long d;
    asm("fma.rn.f32x2 %0, %1, %2, %3;" : "=l"(d) : "l"(a), "l"(b), "l"(c));
    return d;
}

// ================= Phase A: xg[r][j] = bias[j] + sum_k in[r][k] * Wih[:,j,k] =================
// Row pairs (2m, 2m+1) processed packed in f32x2. Splatted weights in SMEM.

template<int JN>
__device__ __forceinline__ void chunkA(const unsigned long long* __restrict__ Ws,
                                       const unsigned long long* __restrict__ Bs,
                                       const unsigned long long* px,
                                       int jbase, float4* __restrict__ outp)
{
    unsigned long long acc[JN][4];
#pragma unroll
    for (int jj = 0; jj < JN; ++jj) {
#pragma unroll
        for (int g = 0; g < 4; ++g) acc[jj][g] = Bs[(jbase + jj) * 4 + g];
    }
#pragma unroll
    for (int k = 0; k < HH; ++k) {
        unsigned long long xk = px[k];
#pragma unroll
        for (int jj = 0; jj < JN; ++jj) {
            const ulonglong2* wp =
                reinterpret_cast<const ulonglong2*>(Ws + ((size_t)(k * HH + jbase + jj)) * 4);
            ulonglong2 w01 = wp[0];
            ulonglong2 w23 = wp[1];
            acc[jj][0] = fma2(xk, w01.x, acc[jj][0]);
            acc[jj][1] = fma2(xk, w01.y, acc[jj][1]);
            acc[jj][2] = fma2(xk, w23.x, acc[jj][2]);
            acc[jj][3] = fma2(xk, w23.y, acc[jj][3]);
        }
    }
#pragma unroll
    for (int jj = 0; jj < JN; ++jj) {
        float4 lo4, hi4;
        unpack2(acc[jj][0], lo4.x, hi4.x);
        unpack2(acc[jj][1], lo4.y, hi4.y);
        unpack2(acc[jj][2], lo4.z, hi4.z);
        unpack2(acc[jj][3], lo4.w, hi4.w);
        outp[jbase + jj]      = lo4;  // row 2m
        outp[HH + jbase + jj] = hi4;  // row 2m+1
    }
}

__global__ void __launch_bounds__(128, 3)
phaseA_kernel(const float* __restrict__ xin,        // used when src==0
              const float* __restrict__ Wih,
              const float* __restrict__ bih,
              const float* __restrict__ bhh,
              int src)                               // 0: xin, 1: g_hbuf (device-side select)
{
    __shared__ alignas(16) unsigned long long Ws[HH * HH * 4];  // [k][j][g] splat pairs
    __shared__ unsigned long long Bs[HH * 4];

    const int tid = threadIdx.x;
    for (int i = tid; i < HH * HH * 4; i += 128) {
        int g = i & 3, j = (i >> 2) % HH, k = (i >> 2) / HH;
        float w = Wih[(g * HH + j) * HH + k];
        Ws[i] = pack2(w, w);
    }
    for (int i = tid; i < HH * 4; i += 128) {
        int g = i & 3, j = i >> 2;
        float b = bih[g * HH + j] + bhh[g * HH + j];
        Bs[i] = pack2(b, b);
    }
    __syncthreads();

    // Device-side selection of the input buffer (device globals never cross host boundary)
    const float* in = (src == 0) ? xin : (const float*)g_hbuf;

    const size_t m = (size_t)blockIdx.x * 128 + tid;  // row-pair index; grid covers exactly
    const float* xr = in + m * (2 * HH);

    unsigned long long px[HH];
#pragma unroll
    for (int k = 0; k < HH; ++k) px[k] = pack2(xr[k], xr[k + HH]);

    float4* outp = g_xg + m * (2 * HH);
    chunkA<7>(Ws, Bs, px, 0,  outp);
    chunkA<7>(Ws, Bs, px, 7,  outp);
    chunkA<7>(Ws, Bs, px, 14, outp);
    chunkA<6>(Ws, Bs, px, 21, outp);
}

// ================= Phase B: recurrence. One warp per batch element; lane j owns gate column j.
// Whh columns live in registers; h exchanged via per-warp SMEM row; c is one register.
// DOLIN=true writes the fused linear head to dout; DOLIN=false writes h to g_hbuf (device-side).

template<bool DOLIN>
__global__ void __launch_bounds__(128, 3)
phaseB_kernel(const float* __restrict__ h0,
              const float* __restrict__ c0,
              const float* __restrict__ Whh,
              const float* __restrict__ Wl,
              const float* __restrict__ bl,
              float* __restrict__ dout)
{
    __shared__ float hs[2][4][32];
    __shared__ float Wls[HH][HH];
    __shared__ float bls[HH];

    const int tid = threadIdx.x;
    const int w   = tid >> 5;
    const int j   = tid & 31;
    const bool act = (j < HH);
    const int jj = act ? j : 0;

    if (DOLIN) {
        for (int i = tid; i < HH * HH; i += 128) Wls[i / HH][i % HH] = Wl[i];
        if (tid < HH) bls[tid] = bl[tid];
        __syncthreads();
    }

    const size_t b = (size_t)blockIdx.x * 4 + w;

    // Whh gate columns in registers (loaded once; uniform across warps -> L2 broadcast)
    float wr0[HH], wr1[HH], wr2[HH], wr3[HH];
#pragma unroll
    for (int k = 0; k < HH; ++k) {
        wr0[k] = Whh[(0 * HH + jj) * HH + k];
        wr1[k] = Whh[(1 * HH + jj) * HH + k];
        wr2[k] = Whh[(2 * HH + jj) * HH + k];
        wr3[k] = Whh[(3 * HH + jj) * HH + k];
    }

    float c = act ? c0[b * HH + j] : 0.f;
    if (act) hs[0][w][j] = h0[b * HH + j];
    __syncwarp();

    const float4* xp = g_xg + b * (size_t)(TT * HH);
    float* op = (DOLIN ? dout : g_hbuf) + b * (size_t)(TT * HH);   // device-side select

    float4 xv = act ? xp[j] : make_float4(0.f, 0.f, 0.f, 0.f);
    int p = 0;

    for (int t = 0; t < TT; ++t) {
        float4 xn = make_float4(0.f, 0.f, 0.f, 0.f);
        if (t + 1 < TT && act) xn = xp[(t + 1) * HH + j];   // prefetch next timestep

        float4 a = xv;
#pragma unroll
        for (int k = 0; k < HH; ++k) {
            float hk = hs[p][w][k];          // broadcast LDS
            a.x = fmaf(wr0[k], hk, a.x);
            a.y = fmaf(wr1[k], hk, a.y);
            a.z = fmaf(wr2[k], hk, a.z);
            a.w = fmaf(wr3[k], hk, a.w);
        }

        float ig = sigf(a.x);
        float fg = sigf(a.y);
        float gg = tanhfast(a.z);
        float og = sigf(a.w);
        c = fmaf(fg, c, ig * gg);
        float hn = og * tanhfast(c);

        if (act) hs[p ^ 1][w][j] = hn;
        __syncwarp();

        if (DOLIN) {
            float acc = bls[jj];
#pragma unroll
            for (int k = 0; k < HH; ++k) acc = fmaf(Wls[jj][k], hs[p ^ 1][w][k], acc);
            if (act) op[t * HH + j] = acc;
        } else {
            if (act) op[t * HH + j] = hn;
        }

        p ^= 1;
        xv = xn;
    }
}

// ================= host =================
extern "C" void kernel_launch(void* const* d_in, const int* in_sizes, int n_in,
                              void* d_out, int out_size)
{
    const float* x   = (const float*)d_in[0];
    const float* h0  = (const float*)d_in[1];
    const float* c0  = (const float*)d_in[2];
    const float* Wih = (const float*)d_in[3];
    const float* Whh = (const float*)d_in[4];
    const float* bih = (const float*)d_in[5];
    const float* bhh = (const float*)d_in[6];
    const float* Wl  = (const float*)d_in[7];
    const float* bl  = (const float*)d_in[8];
    float* out = (float*)d_out;

    const size_t st = (size_t)BB * HH;   // h0/c0 per-layer stride
    const size_t wS = (size_t)GG * HH;   // weight per-layer stride
    const size_t bS = (size_t)GG;        // bias per-layer stride

    const int gridA = (BB * TT / 2) / 128;   // 9984, exact
    const int gridB = BB / 4;                // 8192, exact

    // Layer 0
    phaseA_kernel<<<gridA, 128>>>(x, Wih, bih, bhh, /*src=*/0);
    phaseB_kernel<false><<<gridB, 128>>>(h0, c0, Whh, Wl, bl, out);
    // Layer 1
    phaseA_kernel<<<gridA, 128>>>(x, Wih + wS, bih + bS, bhh + bS, /*src=*/1);
    phaseB_kernel<false><<<gridB, 128>>>(h0 + st, c0 + st, Whh + wS, Wl, bl, out);
    // Layer 2 (+ fused linear head)
    phaseA_kernel<<<gridA, 128>>>(x, Wih + 2 * wS, bih + 2 * bS, bhh + 2 * bS, /*src=*/1);
    phaseB_kernel<true><<<gridB, 128>>>(h0 + 2 * st, c0 + 2 * st, Whh + 2 * wS, Wl, bl, out);
}